// round 2
// baseline (speedup 1.0000x reference)
#include <cuda_runtime.h>
#include <stdint.h>

// Emformer mask constants (compile-time, matching reference)
#define WCOLS  10303u              // (N-1) + RC*N + U = 63 + 2048 + 8192
#define QROW0  2048u               // RC * N
#define SROW0  10240u              // QROW0 + U

__device__ __forceinline__ uint32_t grp8(uint32_t j,
    uint32_t c0, uint32_t c1, uint32_t c2, uint32_t c3,
    uint32_t c4, uint32_t c5, uint32_t c6, uint32_t c7)
{
    return (uint32_t)(j >= c0) + (uint32_t)(j >= c1) + (uint32_t)(j >= c2) +
           (uint32_t)(j >= c3) + (uint32_t)(j >= c4) + (uint32_t)(j >= c5) +
           (uint32_t)(j >= c6) + (uint32_t)(j >= c7);
}

__global__ void __launch_bounds__(256, 8)
emformer_mask_kernel(
    const int* __restrict__ indices,    // (63,) int32
    const int* __restrict__ last_idx,   // (1,)  int32
    const int* __restrict__ rc_tile,    // (63,9)  bool stored as 4-byte (f32/i32)
    const int* __restrict__ rc_last,    // (9,)
    const int* __restrict__ s_tile,     // (63,9)
    const int* __restrict__ s_last,     // (9,)
    float* __restrict__ out)            // (10304, 10303) float32
{
    const int b = blockIdx.x;

    int p;                 // segment slot 0..63
    uint32_t row0, nrows;
    bool use_s;
    if (b < 64) {                       // rc block: 32 rows / segment
        p = b; row0 = (uint32_t)b * 32u; nrows = 32u; use_s = false;
    } else if (b < 320) {               // q block: 128 rows / segment, 4 units of 32
        int u = b - 64;
        p = u >> 2;
        row0 = QROW0 + (uint32_t)p * 128u + (uint32_t)(u & 3) * 32u;
        nrows = 32u; use_s = false;
    } else {                            // s block: 1 row / segment
        p = b - 320; row0 = SROW0 + (uint32_t)p; nrows = 1u; use_s = true;
    }

    const int sid = (p < 63) ? indices[p] : last_idx[0];

    // Sorted cumulative group-end thresholds (element columns) for this segment
    const uint32_t c0 = (uint32_t)max(0, sid - 4);
    const uint32_t c1 = (uint32_t)sid;
    const uint32_t c2 = 63u;
    const uint32_t c3 = 63u + 32u * (uint32_t)sid;
    const uint32_t c4 = c3 + 32u;
    const uint32_t c5 = 2111u;
    const uint32_t c6 = 2111u + (uint32_t)max(0, 128 * sid - 64);
    const uint32_t c7 = 2111u + (uint32_t)min(8192, 128 * (sid + 1));

    // 9-bit pattern: bit k = NOT mask[k]  (output = logical_not of attend-mask)
    // Mask elements are 4-byte (float32 1.0/0.0 or int32 1/0) — nonzero test
    // works for both representations.
    const int* m = use_s ? ((p < 63) ? s_tile + p * 9 : s_last)
                         : ((p < 63) ? rc_tile + p * 9 : rc_last);
    uint32_t pat = 0;
#pragma unroll
    for (int k = 0; k < 9; k++)
        pat |= (uint32_t)(m[k] == 0) << k;

    const uint32_t elem0 = row0 * WCOLS;            // < 1.07e8, fits uint32
    const uint32_t elemN = elem0 + nrows * WCOLS;

    const uint32_t a0 = (elem0 + 15u) & ~15u;       // first 16-elem aligned idx
    const uint32_t aN = elemN & ~15u;               // last  16-elem aligned end
    const uint32_t tid = threadIdx.x;
    const uint32_t nthr = blockDim.x;

    // ---- head: [elem0, min(a0, elemN)) per-element ----
    {
        const uint32_t hEnd = (a0 < elemN) ? a0 : elemN;
        for (uint32_t e = elem0 + tid; e < hEnd; e += nthr) {
            uint32_t col = e % WCOLS;
            out[e] = (float)((pat >> grp8(col, c0,c1,c2,c3,c4,c5,c6,c7)) & 1u);
        }
    }

    // ---- main: 16-element (64B) chunks over [a0, aN) ----
    if (a0 < aN) {
        for (uint32_t e = a0 + tid * 16u; e < aN; e += nthr * 16u) {
            uint32_t col = e % WCOLS;
            if (col + 16u <= WCOLS) {
                uint32_t gA = grp8(col,        c0,c1,c2,c3,c4,c5,c6,c7);
                uint32_t gB = grp8(col + 15u,  c0,c1,c2,c3,c4,c5,c6,c7);
                if (gA == gB) {
                    float v = (float)((pat >> gA) & 1u);
                    float4 q = make_float4(v, v, v, v);
                    float4* o = (float4*)(out + e);
                    o[0] = q; o[1] = q; o[2] = q; o[3] = q;
                    continue;
                }
            }
            // slow path: 4-element sub-chunks, per-element when still mixed
#pragma unroll
            for (int s4 = 0; s4 < 4; s4++) {
                uint32_t ee = e + (uint32_t)s4 * 4u;
                uint32_t cc = ee % WCOLS;
                if (cc + 4u <= WCOLS) {
                    uint32_t gA = grp8(cc,       c0,c1,c2,c3,c4,c5,c6,c7);
                    uint32_t gB = grp8(cc + 3u,  c0,c1,c2,c3,c4,c5,c6,c7);
                    if (gA == gB) {
                        float v = (float)((pat >> gA) & 1u);
                        *(float4*)(out + ee) = make_float4(v, v, v, v);
                        continue;
                    }
                }
                for (uint32_t bb = 0; bb < 4u; bb++) {
                    uint32_t ei = ee + bb;
                    uint32_t col2 = ei % WCOLS;
                    out[ei] = (float)((pat >> grp8(col2, c0,c1,c2,c3,c4,c5,c6,c7)) & 1u);
                }
            }
        }
    }

    // ---- tail: [max(aN, head end), elemN) per-element ----
    {
        uint32_t hEnd = (a0 < elemN) ? a0 : elemN;
        uint32_t tStart = (aN > hEnd) ? aN : hEnd;
        for (uint32_t e = tStart + tid; e < elemN; e += nthr) {
            uint32_t col = e % WCOLS;
            out[e] = (float)((pat >> grp8(col, c0,c1,c2,c3,c4,c5,c6,c7)) & 1u);
        }
    }
}

extern "C" void kernel_launch(void* const* d_in, const int* in_sizes, int n_in,
                              void* d_out, int out_size)
{
    // metadata order: indices, utt_lengths(unused), rc_q_cols_mask_tile,
    //                 last_idx, last_utt_lengths(unused), last_rc_q_cols_mask,
    //                 s_cols_mask_tile, last_s_cols_mask
    const int* indices  = (const int*)d_in[0];
    const int* rc_tile  = (const int*)d_in[2];
    const int* last_idx = (const int*)d_in[3];
    const int* rc_last  = (const int*)d_in[5];
    const int* s_tile   = (const int*)d_in[6];
    const int* s_last   = (const int*)d_in[7];
    float*     out      = (float*)d_out;

    // 64 rc units (32 rows) + 256 q units (32 rows) + 64 s rows = 384 CTAs
    emformer_mask_kernel<<<384, 256>>>(indices, last_idx, rc_tile, rc_last,
                                       s_tile, s_last, out);
}

// round 3
// speedup vs baseline: 2.1706x; 2.1706x over previous
#include <cuda_runtime.h>
#include <stdint.h>

// Emformer mask constants (compile-time, matching reference)
#define WCOLS  10303u              // (N-1) + RC*N + U = 63 + 2048 + 8192
#define NROWS  10304u              // RC*N + U + N
#define QROW0  2048u               // RC * N
#define SROW0  10240u              // QROW0 + U

__device__ __forceinline__ uint32_t grp8(uint32_t j,
    uint32_t c0, uint32_t c1, uint32_t c2, uint32_t c3,
    uint32_t c4, uint32_t c5, uint32_t c6, uint32_t c7)
{
    return (uint32_t)(j >= c0) + (uint32_t)(j >= c1) + (uint32_t)(j >= c2) +
           (uint32_t)(j >= c3) + (uint32_t)(j >= c4) + (uint32_t)(j >= c5) +
           (uint32_t)(j >= c6) + (uint32_t)(j >= c7);
}

__global__ void __launch_bounds__(256)
emformer_mask_kernel(
    const int* __restrict__ indices,    // (63,) int32
    const int* __restrict__ last_idx,   // (1,)  int32
    const int* __restrict__ rc_tile,    // (63,9) bool as 4-byte
    const int* __restrict__ rc_last,    // (9,)
    const int* __restrict__ s_tile,     // (63,9)
    const int* __restrict__ s_last,     // (9,)
    float* __restrict__ out)            // (10304, 10303) float32
{
    const uint32_t r = blockIdx.x;      // one CTA per output row

    int p;            // segment slot 0..63
    bool use_s;
    if (r < QROW0)      { p = (int)(r >> 5);               use_s = false; }
    else if (r < SROW0) { p = (int)((r - QROW0) >> 7);     use_s = false; }
    else                { p = (int)(r - SROW0);            use_s = true;  }

    const int sid = (p < 63) ? indices[p] : last_idx[0];

    // Sorted cumulative group-end thresholds (row-relative columns)
    const uint32_t c0 = (uint32_t)max(0, sid - 4);
    const uint32_t c1 = (uint32_t)sid;
    const uint32_t c2 = 63u;
    const uint32_t c3 = 63u + 32u * (uint32_t)sid;
    const uint32_t c4 = c3 + 32u;
    const uint32_t c5 = 2111u;
    const uint32_t c6 = 2111u + (uint32_t)max(0, 128 * sid - 64);
    const uint32_t c7 = 2111u + (uint32_t)min(8192, 128 * (sid + 1));

    // 9-bit pattern: bit k = NOT mask[k]  (output = logical_not of attend-mask)
    const int* m = use_s ? ((p < 63) ? s_tile + p * 9 : s_last)
                         : ((p < 63) ? rc_tile + p * 9 : rc_last);
    uint32_t pat = 0;
#pragma unroll
    for (int k = 0; k < 9; k++)
        pat |= (uint32_t)(m[k] == 0) << k;

    const uint32_t elem0 = r * WCOLS;          // row start (global elem idx)
    const uint32_t elemN = elem0 + WCOLS;
    const uint32_t a0 = (elem0 + 3u) & ~3u;    // first 16B-aligned elem
    const uint32_t aN = elemN & ~3u;           // last  16B-aligned end
    const uint32_t tid = threadIdx.x;

    // head (<=3 elems) + tail (<=3 elems), by low threads
    if (tid < 8u) {
        uint32_t e = (tid < 4u) ? (elem0 + tid) : (aN + (tid - 4u));
        bool ok = (tid < 4u) ? (e < a0) : (e < elemN);
        if (ok) {
            uint32_t col = e - elem0;
            out[e] = (float)((pat >> grp8(col, c0,c1,c2,c3,c4,c5,c6,c7)) & 1u);
        }
    }

    // main: coalesced float4 stores — consecutive threads, consecutive 16B
    for (uint32_t a = a0 + 4u * tid; a < aN; a += 4u * 256u) {
        uint32_t col = a - elem0;
        uint32_t gA = grp8(col,      c0,c1,c2,c3,c4,c5,c6,c7);
        uint32_t gB = grp8(col + 3u, c0,c1,c2,c3,c4,c5,c6,c7);
        float4 q;
        if (gA == gB) {
            float v = (float)((pat >> gA) & 1u);
            q = make_float4(v, v, v, v);
        } else {
            q.x = (float)((pat >> gA) & 1u);
            q.y = (float)((pat >> grp8(col + 1u, c0,c1,c2,c3,c4,c5,c6,c7)) & 1u);
            q.z = (float)((pat >> grp8(col + 2u, c0,c1,c2,c3,c4,c5,c6,c7)) & 1u);
            q.w = (float)((pat >> gB) & 1u);
        }
        *(float4*)(out + a) = q;
    }
}

extern "C" void kernel_launch(void* const* d_in, const int* in_sizes, int n_in,
                              void* d_out, int out_size)
{
    // metadata order: indices, utt_lengths(unused), rc_q_cols_mask_tile,
    //                 last_idx, last_utt_lengths(unused), last_rc_q_cols_mask,
    //                 s_cols_mask_tile, last_s_cols_mask
    const int* indices  = (const int*)d_in[0];
    const int* rc_tile  = (const int*)d_in[2];
    const int* last_idx = (const int*)d_in[3];
    const int* rc_last  = (const int*)d_in[5];
    const int* s_tile   = (const int*)d_in[6];
    const int* s_last   = (const int*)d_in[7];
    float*     out      = (float*)d_out;

    emformer_mask_kernel<<<NROWS, 256>>>(indices, last_idx, rc_tile, rc_last,
                                         s_tile, s_last, out);
}

// round 4
// speedup vs baseline: 2.2791x; 1.0500x over previous
#include <cuda_runtime.h>
#include <stdint.h>

// Emformer mask constants (compile-time, matching reference)
#define WCOLS  10303u              // (N-1) + RC*N + U = 63 + 2048 + 8192
#define NROWS  10304u              // RC*N + U + N
#define QROW0  2048u               // RC * N
#define SROW0  10240u              // QROW0 + U

// value at relative col j for a 2-threshold zone (x <= y):
//   j < x -> v0 ; x <= j < y -> v1 ; j >= y -> v2
__device__ __forceinline__ float selv(uint32_t j, uint32_t x, uint32_t y,
                                      float v0, float v1, float v2)
{
    return (j >= y) ? v2 : ((j >= x) ? v1 : v0);
}

// Fill out[e0..e1) (global element indices), col = e - elem0.
__device__ __forceinline__ void zone_fill(float* __restrict__ out,
    uint32_t elem0, uint32_t e0, uint32_t e1,
    uint32_t x, uint32_t y, float v0, float v1, float v2, uint32_t tid)
{
    const uint32_t aA = (e0 + 3u) & ~3u;     // first 16B-aligned elem
    const uint32_t aB = e1 & ~3u;            // last  16B-aligned end
    const uint32_t hEnd = (aA < e1) ? aA : e1;

    // head (<=3) + tail (<=3) scalars by low threads
    if (tid < 8u) {
        uint32_t e, lim;
        if (tid < 4u) { e = e0 + tid; lim = hEnd; }
        else {
            uint32_t tS = (aB > hEnd) ? aB : hEnd;
            e = tS + (tid - 4u); lim = e1;
        }
        if (e < lim)
            __stcs(out + e, selv(e - elem0, x, y, v0, v1, v2));
    }

    // j+3 >= x  <=>  j >= x-3 (clamped); clamping only forces the (correct)
    // slow path for the few cols below a tiny threshold.
    const uint32_t xm3 = (x > 3u) ? x - 3u : 0u;
    const uint32_t ym3 = (y > 3u) ? y - 3u : 0u;

    for (uint32_t a = aA + 4u * tid; a < aB; a += 4u * 256u) {
        const uint32_t j = a - elem0;
        const bool px = j >= x,   py = j >= y;
        const bool qx = j >= xm3, qy = j >= ym3;   // endpoint j+3
        float4 q;
        if ((px == qx) & (py == qy)) {             // no threshold inside span
            const float v = py ? v2 : (px ? v1 : v0);
            q = make_float4(v, v, v, v);
        } else {                                   // rare: boundary span
            q.x = selv(j,      x, y, v0, v1, v2);
            q.y = selv(j + 1u, x, y, v0, v1, v2);
            q.z = selv(j + 2u, x, y, v0, v1, v2);
            q.w = selv(j + 3u, x, y, v0, v1, v2);
        }
        __stcs((float4*)(out + a), q);
    }
}

__global__ void __launch_bounds__(256)
emformer_mask_kernel(
    const int* __restrict__ indices,    // (63,) int32
    const int* __restrict__ last_idx,   // (1,)  int32
    const int* __restrict__ rc_tile,    // (63,9) bool as 4-byte
    const int* __restrict__ rc_last,    // (9,)
    const int* __restrict__ s_tile,     // (63,9)
    const int* __restrict__ s_last,     // (9,)
    float* __restrict__ out)            // (10304, 10303) float32
{
    const uint32_t r = blockIdx.x;      // one CTA per output row
    const uint32_t tid = threadIdx.x;

    int p;            // segment slot 0..63
    bool use_s;
    if (r < QROW0)      { p = (int)(r >> 5);           use_s = false; }
    else if (r < SROW0) { p = (int)((r - QROW0) >> 7); use_s = false; }
    else                { p = (int)(r - SROW0);        use_s = true;  }

    const int sid = (p < 63) ? indices[p] : last_idx[0];

    // Per-zone live thresholds (cols): zone A [0,63), B [63,2111), C [2111,W)
    const uint32_t cA0 = (uint32_t)max(0, sid - 4);
    const uint32_t cA1 = (uint32_t)sid;
    const uint32_t cB0 = 63u + 32u * (uint32_t)sid;
    const uint32_t cB1 = cB0 + 32u;
    const uint32_t cC0 = 2111u + (uint32_t)max(0, 128 * sid - 64);
    const uint32_t cC1 = 2111u + (uint32_t)min(8192, 128 * (sid + 1));

    // 9-bit pattern: bit k = NOT mask[k] (output = logical_not of attend-mask)
    const int* m = use_s ? ((p < 63) ? s_tile + p * 9 : s_last)
                         : ((p < 63) ? rc_tile + p * 9 : rc_last);
    uint32_t pat = 0;
#pragma unroll
    for (int k = 0; k < 9; k++)
        pat |= (uint32_t)(m[k] == 0) << k;

    const float f0 = (float)((pat >> 0) & 1u), f1 = (float)((pat >> 1) & 1u),
                f2 = (float)((pat >> 2) & 1u), f3 = (float)((pat >> 3) & 1u),
                f4 = (float)((pat >> 4) & 1u), f5 = (float)((pat >> 5) & 1u),
                f6 = (float)((pat >> 6) & 1u), f7 = (float)((pat >> 7) & 1u),
                f8 = (float)((pat >> 8) & 1u);

    const uint32_t elem0 = r * WCOLS;   // < 1.07e8, fits uint32

    zone_fill(out, elem0, elem0,         elem0 + 63u,    cA0, cA1, f0, f1, f2, tid);
    zone_fill(out, elem0, elem0 + 63u,   elem0 + 2111u,  cB0, cB1, f3, f4, f5, tid);
    zone_fill(out, elem0, elem0 + 2111u, elem0 + WCOLS,  cC0, cC1, f6, f7, f8, tid);
}

extern "C" void kernel_launch(void* const* d_in, const int* in_sizes, int n_in,
                              void* d_out, int out_size)
{
    // metadata order: indices, utt_lengths(unused), rc_q_cols_mask_tile,
    //                 last_idx, last_utt_lengths(unused), last_rc_q_cols_mask,
    //                 s_cols_mask_tile, last_s_cols_mask
    const int* indices  = (const int*)d_in[0];
    const int* rc_tile  = (const int*)d_in[2];
    const int* last_idx = (const int*)d_in[3];
    const int* rc_last  = (const int*)d_in[5];
    const int* s_tile   = (const int*)d_in[6];
    const int* s_last   = (const int*)d_in[7];
    float*     out      = (float*)d_out;

    emformer_mask_kernel<<<NROWS, 256>>>(indices, last_idx, rc_tile, rc_last,
                                         s_tile, s_last, out);
}